// round 8
// baseline (speedup 1.0000x reference)
#include <cuda_runtime.h>
#include <cstdint>
#include <math.h>

#define NN 50000
#define HH 128
#define TT 4
#define EE 150000
#define G3H 384

// ---------------- scratch ---------------------------------------------------
__device__ __align__(16) float g_h  [(size_t)NN * HH];
__device__ __align__(16) float g_inc[(size_t)NN * HH];
__device__ __align__(16) float g_m  [(size_t)TT * NN * HH];
__device__ __align__(16) float g_gh [(size_t)NN * G3H];
__device__ __align__(16) float g_gxx[(size_t)NN * G3H];

// ---------------- utility kernels ------------------------------------------
__global__ void zero4_kernel(float4* __restrict__ p, int n4) {
    int i = blockIdx.x * blockDim.x + threadIdx.x;
    if (i < n4) p[i] = make_float4(0.f, 0.f, 0.f, 0.f);
}
__global__ void copy4_kernel(float4* __restrict__ dst, const float4* __restrict__ src, int n4) {
    int i = blockIdx.x * blockDim.x + threadIdx.x;
    if (i < n4) dst[i] = src[i];
}

// ---------------- scatter: inc[tgt] += m[t][src] ---------------------------
__global__ void scatter_kernel(const int* __restrict__ edges,
                               const float* __restrict__ m,
                               float* __restrict__ inc) {
    int e = blockIdx.x * 8 + (threadIdx.x >> 5);
    if (e >= TT * EE) return;
    int lane = threadIdx.x & 31;
    int t   = e / EE;
    int src = edges[2 * e];
    int tgt = edges[2 * e + 1];
    float4 v = *(const float4*)(m + ((size_t)t * NN + (size_t)src) * HH + lane * 4);
    float* dst = inc + (size_t)tgt * HH + lane * 4;
    asm volatile("red.global.add.v4.f32 [%0], {%1, %2, %3, %4};"
                 :: "l"(dst), "f"(v.x), "f"(v.y), "f"(v.z), "f"(v.w)
                 : "memory");
}

// ---------------- common MMA bits ------------------------------------------
__device__ __forceinline__ void mma8(float* d, const uint32_t* a, const uint32_t* b) {
    asm volatile(
        "mma.sync.aligned.m16n8k8.row.col.f32.tf32.tf32.f32 "
        "{%0,%1,%2,%3}, {%4,%5,%6,%7}, {%8,%9}, {%0,%1,%2,%3};"
        : "+f"(d[0]), "+f"(d[1]), "+f"(d[2]), "+f"(d[3])
        : "r"(a[0]), "r"(a[1]), "r"(a[2]), "r"(a[3]), "r"(b[0]), "r"(b[1]));
}
__device__ __forceinline__ uint4 cvt4(float4 v) {
    uint4 u;
    asm("cvt.rna.tf32.f32 %0, %1;" : "=r"(u.x) : "f"(v.x));
    asm("cvt.rna.tf32.f32 %0, %1;" : "=r"(u.y) : "f"(v.y));
    asm("cvt.rna.tf32.f32 %0, %1;" : "=r"(u.z) : "f"(v.z));
    asm("cvt.rna.tf32.f32 %0, %1;" : "=r"(u.w) : "f"(v.w));
    return u;
}

extern __shared__ uint32_t gsm[];

// ---------------- tf32 mma.sync GEMM: C = A @ B^T (+bias +Cin) -------------
#define KCH 64
#define SPITCH 68
#define ATILE (128 * SPITCH)
#define GEMM_SMEM (2 * ATILE * 4)

__global__ __launch_bounds__(256, 2)
void gemm_tc(const float* __restrict__ A,
             const float* __restrict__ B, int ldb, long sBz,
             const float* __restrict__ Cin,
             float* __restrict__ C, int ldc, long sCz,
             const float* __restrict__ bias, int sBiasZ,
             int M) {
    uint32_t* As = gsm;
    uint32_t* Bs = gsm + ATILE;

    int tid  = threadIdx.x;
    int wid  = tid >> 5;
    int lane = tid & 31;
    int wm   = wid & 1;
    int wn   = wid >> 1;
    int g    = lane >> 2;
    int tg   = lane & 3;

    int z    = blockIdx.z;
    int row0 = blockIdx.y * 128;
    int col0 = blockIdx.x * 128;
    const float* Bz = B + (long)z * sBz;
    float* Cz = C + (long)z * sCz;

    float acc[4][4][4];
#pragma unroll
    for (int i = 0; i < 4; i++)
#pragma unroll
        for (int j = 0; j < 4; j++)
#pragma unroll
            for (int k = 0; k < 4; k++) acc[i][j][k] = 0.f;

    for (int kc = 0; kc < 128; kc += KCH) {
#pragma unroll
        for (int i = 0; i < 8; i++) {
            int id = tid + 256 * i;
            int r  = id >> 4;
            int c4 = (id & 15) << 2;
            float4 va = make_float4(0.f, 0.f, 0.f, 0.f);
            if (row0 + r < M) va = *(const float4*)(A + (long)(row0 + r) * HH + kc + c4);
            *(uint4*)(As + r * SPITCH + c4) = cvt4(va);
            float4 vb = *(const float4*)(Bz + (long)(col0 + r) * ldb + kc + c4);
            *(uint4*)(Bs + r * SPITCH + c4) = cvt4(vb);
        }
        __syncthreads();
#pragma unroll
        for (int ks = 0; ks < 8; ks++) {
            int k0 = ks * 8;
            uint32_t af[4][4], bf[4][2];
#pragma unroll
            for (int mt = 0; mt < 4; mt++) {
                int r = wm * 64 + mt * 16 + g;
                af[mt][0] = As[(r    ) * SPITCH + k0 + tg];
                af[mt][1] = As[(r + 8) * SPITCH + k0 + tg];
                af[mt][2] = As[(r    ) * SPITCH + k0 + tg + 4];
                af[mt][3] = As[(r + 8) * SPITCH + k0 + tg + 4];
            }
#pragma unroll
            for (int nt = 0; nt < 4; nt++) {
                int c = wn * 32 + nt * 8 + g;
                bf[nt][0] = Bs[c * SPITCH + k0 + tg];
                bf[nt][1] = Bs[c * SPITCH + k0 + tg + 4];
            }
#pragma unroll
            for (int mt = 0; mt < 4; mt++)
#pragma unroll
                for (int nt = 0; nt < 4; nt++)
                    mma8(acc[mt][nt], af[mt], bf[nt]);
        }
        __syncthreads();
    }

#pragma unroll
    for (int mt = 0; mt < 4; mt++) {
        int r = row0 + wm * 64 + mt * 16 + g;
#pragma unroll
        for (int nt = 0; nt < 4; nt++) {
            int c = col0 + wn * 32 + nt * 8 + 2 * tg;
            float b0 = 0.f, b1 = 0.f;
            if (bias) {
                const float* bz = bias + (long)z * sBiasZ + c;
                b0 = bz[0]; b1 = bz[1];
            }
            if (r < M) {
                float v0 = acc[mt][nt][0] + b0;
                float v1 = acc[mt][nt][1] + b1;
                if (Cin) {
                    float2 ci = *(const float2*)(Cin + (long)r * ldc + c);
                    v0 += ci.x; v1 += ci.y;
                }
                *(float2*)(Cz + (long)r * ldc + c) = make_float2(v0, v1);
            }
            if (r + 8 < M) {
                float v2 = acc[mt][nt][2] + b0;
                float v3 = acc[mt][nt][3] + b1;
                if (Cin) {
                    float2 ci = *(const float2*)(Cin + (long)(r + 8) * ldc + c);
                    v2 += ci.x; v3 += ci.y;
                }
                *(float2*)(Cz + (long)(r + 8) * ldc + c) = make_float2(v2, v3);
            }
        }
    }
}

// ---------------- fused gx-GEMM + GRU gates --------------------------------
// One CTA per 128-node block. inc tile resident (tf32); loops gate chunks of
// Wih in order r -> n -> z, reading gh/addend from gmem, updating h in place.
#define FPITCH 132
#define FTILE (128 * FPITCH)
#define FUSED_SMEM (2 * FTILE * 4)     // 135168 B

__global__ __launch_bounds__(256, 1)
void gru_fused(const float* __restrict__ inc,
               const float* __restrict__ W, int ldw,
               const float* __restrict__ gh,
               const float* __restrict__ bias,   // [384] or null
               const float* __restrict__ cin,    // [M][384] or null
               float* __restrict__ h, int M) {
    uint32_t* As = gsm;
    uint32_t* Ws = gsm + FTILE;

    int tid  = threadIdx.x;
    int wid  = tid >> 5;
    int lane = tid & 31;
    int wm   = wid & 1;
    int wn   = wid >> 1;
    int g    = lane >> 2;
    int tg   = lane & 3;
    int row0 = blockIdx.x * 128;

    // inc tile -> smem (tf32), full K=128
#pragma unroll
    for (int i = 0; i < 16; i++) {
        int id = tid + 256 * i;
        int r  = id >> 5;
        int c4 = (id & 31) << 2;
        float4 v = make_float4(0.f, 0.f, 0.f, 0.f);
        if (row0 + r < M) v = *(const float4*)(inc + (long)(row0 + r) * HH + c4);
        *(uint4*)(As + r * FPITCH + c4) = cvt4(v);
    }

    float keep[4][4][4];
    const int gates[3] = {0, 2, 1};   // r, n, z

#pragma unroll
    for (int gi = 0; gi < 3; gi++) {
        int gate = gates[gi];
        __syncthreads();    // inc tile ready / previous mma reads of Ws done
        // W chunk -> smem (tf32)
#pragma unroll
        for (int i = 0; i < 16; i++) {
            int id = tid + 256 * i;
            int r  = id >> 5;
            int c4 = (id & 31) << 2;
            float4 v = *(const float4*)(W + (long)(gate * 128 + r) * ldw + c4);
            *(uint4*)(Ws + r * FPITCH + c4) = cvt4(v);
        }
        __syncthreads();

        float acc[4][4][4];
#pragma unroll
        for (int i = 0; i < 4; i++)
#pragma unroll
            for (int j = 0; j < 4; j++)
#pragma unroll
                for (int k = 0; k < 4; k++) acc[i][j][k] = 0.f;

#pragma unroll
        for (int ks = 0; ks < 16; ks++) {
            int k0 = ks * 8;
            uint32_t af[4][4], bf[4][2];
#pragma unroll
            for (int mt = 0; mt < 4; mt++) {
                int r = wm * 64 + mt * 16 + g;
                af[mt][0] = As[(r    ) * FPITCH + k0 + tg];
                af[mt][1] = As[(r + 8) * FPITCH + k0 + tg];
                af[mt][2] = As[(r    ) * FPITCH + k0 + tg + 4];
                af[mt][3] = As[(r + 8) * FPITCH + k0 + tg + 4];
            }
#pragma unroll
            for (int nt = 0; nt < 4; nt++) {
                int c = wn * 32 + nt * 8 + g;
                bf[nt][0] = Ws[c * FPITCH + k0 + tg];
                bf[nt][1] = Ws[c * FPITCH + k0 + tg + 4];
            }
#pragma unroll
            for (int mt = 0; mt < 4; mt++)
#pragma unroll
                for (int nt = 0; nt < 4; nt++)
                    mma8(acc[mt][nt], af[mt], bf[nt]);
        }

        // gate epilogue
#pragma unroll
        for (int mt = 0; mt < 4; mt++) {
            int r0 = row0 + wm * 64 + mt * 16 + g;
            int r1 = r0 + 8;
#pragma unroll
            for (int nt = 0; nt < 4; nt++) {
                int cl   = wn * 32 + nt * 8 + 2 * tg;
                int c384 = gate * 128 + cl;
                float a0 = 0.f, a1 = 0.f, a2 = 0.f, a3 = 0.f;
                if (bias) { a0 = bias[c384]; a1 = bias[c384 + 1]; a2 = a0; a3 = a1; }
                float gh0 = 0.f, gh1 = 0.f, gh2 = 0.f, gh3 = 0.f;
                if (r0 < M) {
                    float2 t = *(const float2*)(gh + (long)r0 * G3H + c384);
                    gh0 = t.x; gh1 = t.y;
                    if (cin) {
                        float2 q = *(const float2*)(cin + (long)r0 * G3H + c384);
                        a0 += q.x; a1 += q.y;
                    }
                }
                if (r1 < M) {
                    float2 t = *(const float2*)(gh + (long)r1 * G3H + c384);
                    gh2 = t.x; gh3 = t.y;
                    if (cin) {
                        float2 q = *(const float2*)(cin + (long)r1 * G3H + c384);
                        a2 += q.x; a3 += q.y;
                    }
                }
                float x0 = acc[mt][nt][0] + a0;
                float x1 = acc[mt][nt][1] + a1;
                float x2 = acc[mt][nt][2] + a2;
                float x3 = acc[mt][nt][3] + a3;
                if (gi == 0) {              // r = sigmoid(xr + hr)
                    keep[mt][nt][0] = 1.f / (1.f + expf(-(x0 + gh0)));
                    keep[mt][nt][1] = 1.f / (1.f + expf(-(x1 + gh1)));
                    keep[mt][nt][2] = 1.f / (1.f + expf(-(x2 + gh2)));
                    keep[mt][nt][3] = 1.f / (1.f + expf(-(x3 + gh3)));
                } else if (gi == 1) {       // n = tanh(xn + r*hn)
                    keep[mt][nt][0] = tanhf(x0 + keep[mt][nt][0] * gh0);
                    keep[mt][nt][1] = tanhf(x1 + keep[mt][nt][1] * gh1);
                    keep[mt][nt][2] = tanhf(x2 + keep[mt][nt][2] * gh2);
                    keep[mt][nt][3] = tanhf(x3 + keep[mt][nt][3] * gh3);
                } else {                    // z; h' = n + z*(h - n)
                    float z0 = 1.f / (1.f + expf(-(x0 + gh0)));
                    float z1 = 1.f / (1.f + expf(-(x1 + gh1)));
                    float z2 = 1.f / (1.f + expf(-(x2 + gh2)));
                    float z3 = 1.f / (1.f + expf(-(x3 + gh3)));
                    if (r0 < M) {
                        float2 hv = *(const float2*)(h + (long)r0 * HH + cl);
                        float o0 = keep[mt][nt][0] + z0 * (hv.x - keep[mt][nt][0]);
                        float o1 = keep[mt][nt][1] + z1 * (hv.y - keep[mt][nt][1]);
                        *(float2*)(h + (long)r0 * HH + cl) = make_float2(o0, o1);
                    }
                    if (r1 < M) {
                        float2 hv = *(const float2*)(h + (long)r1 * HH + cl);
                        float o2 = keep[mt][nt][2] + z2 * (hv.x - keep[mt][nt][2]);
                        float o3 = keep[mt][nt][3] + z3 * (hv.y - keep[mt][nt][3]);
                        *(float2*)(h + (long)r1 * HH + cl) = make_float2(o2, o3);
                    }
                }
            }
        }
    }
}

// ---------------- orchestration --------------------------------------------
extern "C" void kernel_launch(void* const* d_in, const int* in_sizes, int n_in,
                              void* d_out, int out_size) {
    const float* x      = (const float*)d_in[0];
    const int*   edges  = (const int*)  d_in[1];
    const float* msg_W  = (const float*)d_in[2];
    const float* msg_b  = (const float*)d_in[3];
    const float* g0Wih  = (const float*)d_in[4];
    const float* g0Whh  = (const float*)d_in[5];
    const float* g0bih  = (const float*)d_in[6];
    const float* g0bhh  = (const float*)d_in[7];
    const float* g1Wih  = (const float*)d_in[8];
    const float* g1Whh  = (const float*)d_in[9];
    const float* g1bih  = (const float*)d_in[10];
    const float* g1bhh  = (const float*)d_in[11];
    float* out = (float*)d_out;

    float *h, *inc, *m, *gh, *gxx;
    cudaGetSymbolAddress((void**)&h,   g_h);
    cudaGetSymbolAddress((void**)&inc, g_inc);
    cudaGetSymbolAddress((void**)&m,   g_m);
    cudaGetSymbolAddress((void**)&gh,  g_gh);
    cudaGetSymbolAddress((void**)&gxx, g_gxx);

    static cudaStream_t s2;
    static cudaEvent_t evA, evB;
    static int inited = 0;
    if (!inited) {
        cudaFuncSetAttribute(gemm_tc,   cudaFuncAttributeMaxDynamicSharedMemorySize, GEMM_SMEM);
        cudaFuncSetAttribute(gru_fused, cudaFuncAttributeMaxDynamicSharedMemorySize, FUSED_SMEM);
        cudaStreamCreateWithFlags(&s2, cudaStreamNonBlocking);
        cudaEventCreateWithFlags(&evA, cudaEventDisableTiming);
        cudaEventCreateWithFlags(&evB, cudaEventDisableTiming);
        inited = 1;
    }

    const int nh4 = NN * HH / 4;
    const int nBlk = (NN + 127) / 128;           // 391

    dim3 gridMsg(1, nBlk, TT);
    dim3 gridG  (3, nBlk, 1);

    // h = x
    copy4_kernel<<<(nh4 + 255) / 256, 256>>>((float4*)h, (const float4*)x, nh4);

    // gxx = x @ Wih1[:, :128]^T + bih1
    gemm_tc<<<gridG, 256, GEMM_SMEM>>>(x, g1Wih, 2 * HH, 0, nullptr,
                                       gxx, G3H, 0, g1bih, 0, NN);

    for (int l = 0; l < 2; l++) {
        const float* Wih  = (l == 0) ? g0Wih : (g1Wih + HH);
        int          ldw  = (l == 0) ? HH : 2 * HH;
        const float* Whh  = (l == 0) ? g0Whh : g1Whh;
        const float* bih  = (l == 0) ? g0bih : nullptr;
        const float* cin  = (l == 0) ? nullptr : gxx;
        const float* bhh  = (l == 0) ? g0bhh : g1bhh;

        for (int step = 0; step < 3; step++) {
            // m_t = h @ W_{l,t}^T + b_{l,t}
            gemm_tc<<<gridMsg, 256, GEMM_SMEM>>>(h,
                                                 msg_W + (size_t)l * TT * HH * HH, HH, (long)HH * HH,
                                                 nullptr,
                                                 m, HH, (long)NN * HH,
                                                 msg_b + (size_t)l * TT * HH, HH, NN);

            // fork: gh = h @ Whh^T + bhh on s2, overlapped with zero+scatter
            cudaEventRecord(evA, 0);
            cudaStreamWaitEvent(s2, evA, 0);
            gemm_tc<<<gridG, 256, GEMM_SMEM, s2>>>(h, Whh, HH, 0, nullptr,
                                                   gh, G3H, 0, bhh, 0, NN);
            cudaEventRecord(evB, s2);

            // inc = 0; inc[tgt] += m_t[src]
            zero4_kernel<<<(nh4 + 255) / 256, 256>>>((float4*)inc, nh4);
            scatter_kernel<<<(TT * EE + 7) / 8, 256>>>(edges, m, inc);

            // join, then fused gx-GEMM + gates (h updated in place)
            cudaStreamWaitEvent(0, evB, 0);
            gru_fused<<<nBlk, 256, FUSED_SMEM>>>(inc, Wih, ldw, gh, bih, cin, h, NN);
        }
    }

    copy4_kernel<<<(nh4 + 255) / 256, 256>>>((float4*)out, (const float4*)h, nh4);
}

// round 9
// speedup vs baseline: 1.2304x; 1.2304x over previous
#include <cuda_runtime.h>
#include <cstdint>
#include <math.h>

#define NN 50000
#define HH 128
#define TT 4
#define EE 150000
#define G3H 384

// ---------------- scratch ---------------------------------------------------
__device__ __align__(16) float g_h  [(size_t)NN * HH];
__device__ __align__(16) float g_inc[(size_t)NN * HH];
__device__ __align__(16) float g_m  [(size_t)TT * NN * HH];
__device__ __align__(16) float g_gx [(size_t)NN * G3H];
__device__ __align__(16) float g_gh [(size_t)NN * G3H];
__device__ __align__(16) float g_gxx[(size_t)NN * G3H];

// ---------------- utility kernels ------------------------------------------
__global__ void zero4_kernel(float4* __restrict__ p, int n4) {
    int i = blockIdx.x * blockDim.x + threadIdx.x;
    if (i < n4) p[i] = make_float4(0.f, 0.f, 0.f, 0.f);
}
__global__ void copy4_kernel(float4* __restrict__ dst, const float4* __restrict__ src, int n4) {
    int i = blockIdx.x * blockDim.x + threadIdx.x;
    if (i < n4) dst[i] = src[i];
}

// ---------------- per-type scatter: inc[tgt] += mt[src] --------------------
__global__ void scatter_t_kernel(const int* __restrict__ edges_t,
                                 const float* __restrict__ mt,
                                 float* __restrict__ inc) {
    int e = blockIdx.x * 8 + (threadIdx.x >> 5);
    if (e >= EE) return;
    int lane = threadIdx.x & 31;
    int src = edges_t[2 * e];
    int tgt = edges_t[2 * e + 1];
    float4 v = *(const float4*)(mt + (size_t)src * HH + lane * 4);
    float* dst = inc + (size_t)tgt * HH + lane * 4;
    asm volatile("red.global.add.v4.f32 [%0], {%1, %2, %3, %4};"
                 :: "l"(dst), "f"(v.x), "f"(v.y), "f"(v.z), "f"(v.w)
                 : "memory");
}

// ---------------- common MMA bits ------------------------------------------
__device__ __forceinline__ void mma8(float* d, const uint32_t* a, const uint32_t* b) {
    asm volatile(
        "mma.sync.aligned.m16n8k8.row.col.f32.tf32.tf32.f32 "
        "{%0,%1,%2,%3}, {%4,%5,%6,%7}, {%8,%9}, {%0,%1,%2,%3};"
        : "+f"(d[0]), "+f"(d[1]), "+f"(d[2]), "+f"(d[3])
        : "r"(a[0]), "r"(a[1]), "r"(a[2]), "r"(a[3]), "r"(b[0]), "r"(b[1]));
}
__device__ __forceinline__ uint4 cvt4(float4 v) {
    uint4 u;
    asm("cvt.rna.tf32.f32 %0, %1;" : "=r"(u.x) : "f"(v.x));
    asm("cvt.rna.tf32.f32 %0, %1;" : "=r"(u.y) : "f"(v.y));
    asm("cvt.rna.tf32.f32 %0, %1;" : "=r"(u.z) : "f"(v.z));
    asm("cvt.rna.tf32.f32 %0, %1;" : "=r"(u.w) : "f"(v.w));
    return u;
}

extern __shared__ uint32_t gsm[];

// ---------------- tf32 mma.sync GEMM: C = A @ B^T (+bias +Cin) -------------
#define KCH 64
#define SPITCH 68
#define ATILE (128 * SPITCH)
#define GEMM_SMEM (2 * ATILE * 4)

__global__ __launch_bounds__(256, 2)
void gemm_tc(const float* __restrict__ A,
             const float* __restrict__ B, int ldb, long sBz,
             const float* __restrict__ Cin,
             float* __restrict__ C, int ldc, long sCz,
             const float* __restrict__ bias, int sBiasZ,
             int M) {
    uint32_t* As = gsm;
    uint32_t* Bs = gsm + ATILE;

    int tid  = threadIdx.x;
    int wid  = tid >> 5;
    int lane = tid & 31;
    int wm   = wid & 1;
    int wn   = wid >> 1;
    int g    = lane >> 2;
    int tg   = lane & 3;

    int z    = blockIdx.z;
    int row0 = blockIdx.y * 128;
    int col0 = blockIdx.x * 128;
    const float* Bz = B + (long)z * sBz;
    float* Cz = C + (long)z * sCz;

    float acc[4][4][4];
#pragma unroll
    for (int i = 0; i < 4; i++)
#pragma unroll
        for (int j = 0; j < 4; j++)
#pragma unroll
            for (int k = 0; k < 4; k++) acc[i][j][k] = 0.f;

    for (int kc = 0; kc < 128; kc += KCH) {
#pragma unroll
        for (int i = 0; i < 8; i++) {
            int id = tid + 256 * i;
            int r  = id >> 4;
            int c4 = (id & 15) << 2;
            float4 va = make_float4(0.f, 0.f, 0.f, 0.f);
            if (row0 + r < M) va = *(const float4*)(A + (long)(row0 + r) * HH + kc + c4);
            *(uint4*)(As + r * SPITCH + c4) = cvt4(va);
            float4 vb = *(const float4*)(Bz + (long)(col0 + r) * ldb + kc + c4);
            *(uint4*)(Bs + r * SPITCH + c4) = cvt4(vb);
        }
        __syncthreads();
#pragma unroll
        for (int ks = 0; ks < 8; ks++) {
            int k0 = ks * 8;
            uint32_t af[4][4], bf[4][2];
#pragma unroll
            for (int mt = 0; mt < 4; mt++) {
                int r = wm * 64 + mt * 16 + g;
                af[mt][0] = As[(r    ) * SPITCH + k0 + tg];
                af[mt][1] = As[(r + 8) * SPITCH + k0 + tg];
                af[mt][2] = As[(r    ) * SPITCH + k0 + tg + 4];
                af[mt][3] = As[(r + 8) * SPITCH + k0 + tg + 4];
            }
#pragma unroll
            for (int nt = 0; nt < 4; nt++) {
                int c = wn * 32 + nt * 8 + g;
                bf[nt][0] = Bs[c * SPITCH + k0 + tg];
                bf[nt][1] = Bs[c * SPITCH + k0 + tg + 4];
            }
#pragma unroll
            for (int mt = 0; mt < 4; mt++)
#pragma unroll
                for (int nt = 0; nt < 4; nt++)
                    mma8(acc[mt][nt], af[mt], bf[nt]);
        }
        __syncthreads();
    }

#pragma unroll
    for (int mt = 0; mt < 4; mt++) {
        int r = row0 + wm * 64 + mt * 16 + g;
#pragma unroll
        for (int nt = 0; nt < 4; nt++) {
            int c = col0 + wn * 32 + nt * 8 + 2 * tg;
            float b0 = 0.f, b1 = 0.f;
            if (bias) {
                const float* bz = bias + (long)z * sBiasZ + c;
                b0 = bz[0]; b1 = bz[1];
            }
            if (r < M) {
                float v0 = acc[mt][nt][0] + b0;
                float v1 = acc[mt][nt][1] + b1;
                if (Cin) {
                    float2 ci = *(const float2*)(Cin + (long)r * ldc + c);
                    v0 += ci.x; v1 += ci.y;
                }
                *(float2*)(Cz + (long)r * ldc + c) = make_float2(v0, v1);
            }
            if (r + 8 < M) {
                float v2 = acc[mt][nt][2] + b0;
                float v3 = acc[mt][nt][3] + b1;
                if (Cin) {
                    float2 ci = *(const float2*)(Cin + (long)(r + 8) * ldc + c);
                    v2 += ci.x; v3 += ci.y;
                }
                *(float2*)(Cz + (long)(r + 8) * ldc + c) = make_float2(v2, v3);
            }
        }
    }
}

// ---------------- GRU gate fusion ------------------------------------------
__global__ void gates_kernel(float* __restrict__ h,
                             const float* __restrict__ gx,
                             const float* __restrict__ gh) {
    int idx = blockIdx.x * blockDim.x + threadIdx.x;
    if (idx >= NN * HH) return;
    int n = idx >> 7;
    int f = idx & 127;
    long base = (long)n * G3H + f;
    float xr = gx[base], xz = gx[base + 128], xn = gx[base + 256];
    float hr = gh[base], hz = gh[base + 128], hn = gh[base + 256];
    float r = 1.f / (1.f + expf(-(xr + hr)));
    float z = 1.f / (1.f + expf(-(xz + hz)));
    float nn = tanhf(xn + r * hn);
    float hv = h[idx];
    h[idx] = (1.f - z) * nn + z * hv;
}

// ---------------- orchestration --------------------------------------------
extern "C" void kernel_launch(void* const* d_in, const int* in_sizes, int n_in,
                              void* d_out, int out_size) {
    const float* x      = (const float*)d_in[0];
    const int*   edges  = (const int*)  d_in[1];
    const float* msg_W  = (const float*)d_in[2];
    const float* msg_b  = (const float*)d_in[3];
    const float* g0Wih  = (const float*)d_in[4];
    const float* g0Whh  = (const float*)d_in[5];
    const float* g0bih  = (const float*)d_in[6];
    const float* g0bhh  = (const float*)d_in[7];
    const float* g1Wih  = (const float*)d_in[8];
    const float* g1Whh  = (const float*)d_in[9];
    const float* g1bih  = (const float*)d_in[10];
    const float* g1bhh  = (const float*)d_in[11];
    float* out = (float*)d_out;

    float *h, *inc, *m, *gx, *gh, *gxx;
    cudaGetSymbolAddress((void**)&h,   g_h);
    cudaGetSymbolAddress((void**)&inc, g_inc);
    cudaGetSymbolAddress((void**)&m,   g_m);
    cudaGetSymbolAddress((void**)&gx,  g_gx);
    cudaGetSymbolAddress((void**)&gh,  g_gh);
    cudaGetSymbolAddress((void**)&gxx, g_gxx);

    static cudaStream_t s2;
    static cudaEvent_t evTop, evT[TT], evS, evGh;
    static int inited = 0;
    if (!inited) {
        cudaFuncSetAttribute(gemm_tc, cudaFuncAttributeMaxDynamicSharedMemorySize, GEMM_SMEM);
        cudaStreamCreateWithFlags(&s2, cudaStreamNonBlocking);
        cudaEventCreateWithFlags(&evTop, cudaEventDisableTiming);
        for (int t = 0; t < TT; t++) cudaEventCreateWithFlags(&evT[t], cudaEventDisableTiming);
        cudaEventCreateWithFlags(&evS,  cudaEventDisableTiming);
        cudaEventCreateWithFlags(&evGh, cudaEventDisableTiming);
        inited = 1;
    }

    const int nh4 = NN * HH / 4;
    const int nBlk = (NN + 127) / 128;           // 391

    dim3 gridMsg(1, nBlk, 1);
    dim3 gridG  (3, nBlk, 1);

    // h = x
    copy4_kernel<<<(nh4 + 255) / 256, 256>>>((float4*)h, (const float4*)x, nh4);

    // gxx = x @ Wih1[:, :128]^T + bih1
    gemm_tc<<<gridG, 256, GEMM_SMEM>>>(x, g1Wih, 2 * HH, 0, nullptr,
                                       gxx, G3H, 0, g1bih, 0, NN);

    for (int l = 0; l < 2; l++) {
        const float* Wl = msg_W + (size_t)l * TT * HH * HH;
        const float* bl = msg_b + (size_t)l * TT * HH;
        const float* Wih = (l == 0) ? g0Wih : (g1Wih + HH);
        int          ldw = (l == 0) ? HH : 2 * HH;
        const float* Whh = (l == 0) ? g0Whh : g1Whh;
        const float* bih = (l == 0) ? g0bih : nullptr;
        const float* cin = (l == 0) ? nullptr : gxx;
        const float* bhh = (l == 0) ? g0bhh : g1bhh;

        for (int step = 0; step < 3; step++) {
            // fork point: previous-step consumers of inc are done on stream 0
            cudaEventRecord(evTop, 0);
            cudaStreamWaitEvent(s2, evTop, 0);

            // s2: zero inc while s1 computes m_0
            zero4_kernel<<<(nh4 + 255) / 256, 256, 0, s2>>>((float4*)inc, nh4);

            // s1: per-type message GEMMs; s2: scatter each type as it lands
            for (int t = 0; t < TT; t++) {
                float* mt = m + (size_t)t * NN * HH;
                gemm_tc<<<gridMsg, 256, GEMM_SMEM>>>(h, Wl + (size_t)t * HH * HH, HH, 0,
                                                     nullptr, mt, HH, 0,
                                                     bl + (size_t)t * HH, 0, NN);
                cudaEventRecord(evT[t], 0);
                cudaStreamWaitEvent(s2, evT[t], 0);
                scatter_t_kernel<<<(EE + 7) / 8, 256, 0, s2>>>(edges + (size_t)t * EE * 2, mt, inc);
            }

            // s1: gh = h @ Whh^T + bhh (independent; overlaps scatters on s2)
            gemm_tc<<<gridG, 256, GEMM_SMEM>>>(h, Whh, HH, 0, nullptr,
                                               gh, G3H, 0, bhh, 0, NN);

            // join: s1 waits for all scatters
            cudaEventRecord(evS, s2);
            cudaStreamWaitEvent(0, evS, 0);

            // gx = inc @ Wih^T (+gxx or +bih)
            gemm_tc<<<gridG, 256, GEMM_SMEM>>>(inc, Wih, ldw, 0, cin,
                                               gx, G3H, 0, bih, 0, NN);

            // gates, h in place
            gates_kernel<<<(NN * HH + 255) / 256, 256>>>(h, gx, gh);
        }
    }

    copy4_kernel<<<(nh4 + 255) / 256, 256>>>((float4*)out, (const float4*)h, nh4);
}

// round 11
// speedup vs baseline: 1.4655x; 1.1910x over previous
#include <cuda_runtime.h>
#include <cstdint>
#include <math.h>

#define NN 50000
#define HH 128
#define TT 4
#define EE 150000
#define G3H 384

// ---------------- scratch ---------------------------------------------------
__device__ __align__(16) float g_inc[(size_t)NN * HH];
__device__ __align__(16) float g_m  [(size_t)TT * NN * HH];
__device__ __align__(16) float g_gx [(size_t)NN * G3H];
__device__ __align__(16) float g_gh [(size_t)NN * G3H];
__device__ __align__(16) float g_gxx[(size_t)NN * G3H];

// ---------------- utility kernels ------------------------------------------
__global__ void zero4_kernel(float4* __restrict__ p, int n4) {
    int i = blockIdx.x * blockDim.x + threadIdx.x;
    if (i < n4) p[i] = make_float4(0.f, 0.f, 0.f, 0.f);
}
__global__ void copy4_kernel(float4* __restrict__ dst, const float4* __restrict__ src, int n4) {
    int i = blockIdx.x * blockDim.x + threadIdx.x;
    if (i < n4) dst[i] = src[i];
}

// ---------------- scatter: inc[tgt] += m[t][src], 4 edges per warp ---------
__global__ void scatter_kernel(const int* __restrict__ edges,
                               const float* __restrict__ m,
                               float* __restrict__ inc) {
    int e0 = (blockIdx.x * 8 + (threadIdx.x >> 5)) * 4;
    int lane = threadIdx.x & 31;
    float4 v[4];
    int tgt[4];
    bool ok[4];
#pragma unroll
    for (int u = 0; u < 4; u++) {
        int e = e0 + u;
        ok[u] = (e < TT * EE);
        if (ok[u]) {
            int t   = e / EE;
            int src = edges[2 * e];
            tgt[u]  = edges[2 * e + 1];
            v[u] = *(const float4*)(m + ((size_t)t * NN + (size_t)src) * HH + lane * 4);
        }
    }
#pragma unroll
    for (int u = 0; u < 4; u++) {
        if (ok[u]) {
            float* dst = inc + (size_t)tgt[u] * HH + lane * 4;
            asm volatile("red.global.add.v4.f32 [%0], {%1, %2, %3, %4};"
                         :: "l"(dst), "f"(v[u].x), "f"(v[u].y), "f"(v[u].z), "f"(v[u].w)
                         : "memory");
        }
    }
}

// ---------------- common MMA bits ------------------------------------------
__device__ __forceinline__ void mma8(float* d, const uint32_t* a, const uint32_t* b) {
    asm volatile(
        "mma.sync.aligned.m16n8k8.row.col.f32.tf32.tf32.f32 "
        "{%0,%1,%2,%3}, {%4,%5,%6,%7}, {%8,%9}, {%0,%1,%2,%3};"
        : "+f"(d[0]), "+f"(d[1]), "+f"(d[2]), "+f"(d[3])
        : "r"(a[0]), "r"(a[1]), "r"(a[2]), "r"(a[3]), "r"(b[0]), "r"(b[1]));
}
__device__ __forceinline__ uint4 cvt4(float4 v) {
    uint4 u;
    asm("cvt.rna.tf32.f32 %0, %1;" : "=r"(u.x) : "f"(v.x));
    asm("cvt.rna.tf32.f32 %0, %1;" : "=r"(u.y) : "f"(v.y));
    asm("cvt.rna.tf32.f32 %0, %1;" : "=r"(u.z) : "f"(v.z));
    asm("cvt.rna.tf32.f32 %0, %1;" : "=r"(u.w) : "f"(v.w));
    return u;
}

extern __shared__ uint32_t gsm[];

#define KCH 64
#define SPITCH 68
#define ATILE (128 * SPITCH)
#define GEMM_SMEM (2 * ATILE * 4)

// core: one 128x128 C tile = A[row0:+128, :128] @ Bt[0:128, :128]^T (+bias +Cin)
// A lda=128. Bt pre-offset to tile start, row stride ldb. C at (row0, ccol).
__device__ __forceinline__ void gemm_core(
    const float* __restrict__ A,
    const float* __restrict__ Bt, int ldb,
    const float* __restrict__ Cin,
    float* __restrict__ C, int ldc, int ccol,
    const float* __restrict__ bias,
    int row0, int M) {
    uint32_t* As = gsm;
    uint32_t* Bs = gsm + ATILE;

    int tid  = threadIdx.x;
    int wid  = tid >> 5;
    int lane = tid & 31;
    int wm   = wid & 1;
    int wn   = wid >> 1;
    int g    = lane >> 2;
    int tg   = lane & 3;

    float acc[4][4][4];
#pragma unroll
    for (int i = 0; i < 4; i++)
#pragma unroll
        for (int j = 0; j < 4; j++)
#pragma unroll
            for (int k = 0; k < 4; k++) acc[i][j][k] = 0.f;

    for (int kc = 0; kc < 128; kc += KCH) {
#pragma unroll
        for (int i = 0; i < 8; i++) {
            int id = tid + 256 * i;
            int r  = id >> 4;
            int c4 = (id & 15) << 2;
            float4 va = make_float4(0.f, 0.f, 0.f, 0.f);
            if (row0 + r < M) va = *(const float4*)(A + (long)(row0 + r) * HH + kc + c4);
            *(uint4*)(As + r * SPITCH + c4) = cvt4(va);
            float4 vb = *(const float4*)(Bt + (long)r * ldb + kc + c4);
            *(uint4*)(Bs + r * SPITCH + c4) = cvt4(vb);
        }
        __syncthreads();
#pragma unroll
        for (int ks = 0; ks < 8; ks++) {
            int k0 = ks * 8;
            uint32_t af[4][4], bf[4][2];
#pragma unroll
            for (int mt = 0; mt < 4; mt++) {
                int r = wm * 64 + mt * 16 + g;
                af[mt][0] = As[(r    ) * SPITCH + k0 + tg];
                af[mt][1] = As[(r + 8) * SPITCH + k0 + tg];
                af[mt][2] = As[(r    ) * SPITCH + k0 + tg + 4];
                af[mt][3] = As[(r + 8) * SPITCH + k0 + tg + 4];
            }
#pragma unroll
            for (int nt = 0; nt < 4; nt++) {
                int c = wn * 32 + nt * 8 + g;
                bf[nt][0] = Bs[c * SPITCH + k0 + tg];
                bf[nt][1] = Bs[c * SPITCH + k0 + tg + 4];
            }
#pragma unroll
            for (int mt = 0; mt < 4; mt++)
#pragma unroll
                for (int nt = 0; nt < 4; nt++)
                    mma8(acc[mt][nt], af[mt], bf[nt]);
        }
        __syncthreads();
    }

#pragma unroll
    for (int mt = 0; mt < 4; mt++) {
        int r = row0 + wm * 64 + mt * 16 + g;
#pragma unroll
        for (int nt = 0; nt < 4; nt++) {
            int cl = wn * 32 + nt * 8 + 2 * tg;
            int c  = ccol + cl;
            float b0 = 0.f, b1 = 0.f;
            if (bias) { b0 = bias[cl]; b1 = bias[cl + 1]; }
            if (r < M) {
                float v0 = acc[mt][nt][0] + b0;
                float v1 = acc[mt][nt][1] + b1;
                if (Cin) {
                    float2 ci = *(const float2*)(Cin + (long)r * ldc + c);
                    v0 += ci.x; v1 += ci.y;
                }
                *(float2*)(C + (long)r * ldc + c) = make_float2(v0, v1);
            }
            if (r + 8 < M) {
                float v2 = acc[mt][nt][2] + b0;
                float v3 = acc[mt][nt][3] + b1;
                if (Cin) {
                    float2 ci = *(const float2*)(Cin + (long)(r + 8) * ldc + c);
                    v2 += ci.x; v3 += ci.y;
                }
                *(float2*)(C + (long)(r + 8) * ldc + c) = make_float2(v2, v3);
            }
        }
    }
}

// generic GEMM (for gxx / gx): grid (colTiles, rowBlocks)
__global__ __launch_bounds__(256, 2)
void gemm_tc(const float* __restrict__ A,
             const float* __restrict__ B, int ldb,
             const float* __restrict__ Cin,
             float* __restrict__ C, int ldc,
             const float* __restrict__ bias,
             int M) {
    int ct = blockIdx.x;
    gemm_core(A, B + (long)ct * 128 * ldb, ldb, Cin, C, ldc, ct * 128,
              bias ? (bias + ct * 128) : nullptr, blockIdx.y * 128, M);
}

// combined h-GEMMs: z<4 -> m_t = h@W_t^T + b_t ; z>=4 -> gh tile = h@Whh^T + bhh
__global__ __launch_bounds__(256, 2)
void gemm_hcomb(const float* __restrict__ h,
                const float* __restrict__ msgW, const float* __restrict__ msgb,
                float* __restrict__ m,
                const float* __restrict__ Whh, const float* __restrict__ bhh,
                float* __restrict__ gh, int M) {
    int z = blockIdx.z;
    if (z < 4) {
        gemm_core(h, msgW + (long)z * HH * HH, HH, nullptr,
                  m + (size_t)z * NN * HH, HH, 0, msgb + z * HH,
                  blockIdx.y * 128, M);
    } else {
        int zz = z - 4;
        gemm_core(h, Whh + (long)zz * 128 * HH, HH, nullptr,
                  gh, G3H, zz * 128, bhh + zz * 128,
                  blockIdx.y * 128, M);
    }
}

// ---------------- GRU gates (+ zero inc for next step) ---------------------
__global__ void gates_kernel(float* __restrict__ h,
                             const float* __restrict__ gx,
                             const float* __restrict__ gh,
                             float* __restrict__ inc) {
    int idx = blockIdx.x * blockDim.x + threadIdx.x;
    if (idx >= NN * HH) return;
    int n = idx >> 7;
    int f = idx & 127;
    long base = (long)n * G3H + f;
    float xr = gx[base], xz = gx[base + 128], xn = gx[base + 256];
    float hr = gh[base], hz = gh[base + 128], hn = gh[base + 256];
    float r = 1.f / (1.f + expf(-(xr + hr)));
    float z = 1.f / (1.f + expf(-(xz + hz)));
    float nn = tanhf(xn + r * hn);
    float hv = h[idx];
    h[idx] = (1.f - z) * nn + z * hv;
    inc[idx] = 0.f;                       // ready for next step's scatter
}

// ---------------- orchestration --------------------------------------------
extern "C" void kernel_launch(void* const* d_in, const int* in_sizes, int n_in,
                              void* d_out, int out_size) {
    const float* x      = (const float*)d_in[0];
    const int*   edges  = (const int*)  d_in[1];
    const float* msg_W  = (const float*)d_in[2];
    const float* msg_b  = (const float*)d_in[3];
    const float* g0Wih  = (const float*)d_in[4];
    const float* g0Whh  = (const float*)d_in[5];
    const float* g0bih  = (const float*)d_in[6];
    const float* g0bhh  = (const float*)d_in[7];
    const float* g1Wih  = (const float*)d_in[8];
    const float* g1Whh  = (const float*)d_in[9];
    const float* g1bih  = (const float*)d_in[10];
    const float* g1bhh  = (const float*)d_in[11];
    float* h = (float*)d_out;            // h lives in the output buffer

    float *inc, *m, *gx, *gh, *gxx;
    cudaGetSymbolAddress((void**)&inc, g_inc);
    cudaGetSymbolAddress((void**)&m,   g_m);
    cudaGetSymbolAddress((void**)&gx,  g_gx);
    cudaGetSymbolAddress((void**)&gh,  g_gh);
    cudaGetSymbolAddress((void**)&gxx, g_gxx);

    static int inited = 0;
    if (!inited) {
        cudaFuncSetAttribute(gemm_tc,    cudaFuncAttributeMaxDynamicSharedMemorySize, GEMM_SMEM);
        cudaFuncSetAttribute(gemm_hcomb, cudaFuncAttributeMaxDynamicSharedMemorySize, GEMM_SMEM);
        inited = 1;
    }

    const int nh4 = NN * HH / 4;
    const int nBlk = (NN + 127) / 128;        // 391
    const int nWarps4 = (TT * EE + 3) / 4;    // warp-groups of 4 edges
    const int scatBlocks = (nWarps4 + 7) / 8; // 8 warps per block

    dim3 gridHC(1, nBlk, 7);
    dim3 gridG (3, nBlk, 1);

    // h = x ; inc = 0
    copy4_kernel<<<(nh4 + 255) / 256, 256>>>((float4*)h, (const float4*)x, nh4);
    zero4_kernel<<<(nh4 + 255) / 256, 256>>>((float4*)inc, nh4);

    // gxx = x @ Wih1[:, :128]^T + bih1
    gemm_tc<<<gridG, 256, GEMM_SMEM>>>(x, g1Wih, 2 * HH, nullptr,
                                       gxx, G3H, g1bih, NN);

    for (int l = 0; l < 2; l++) {
        const float* Wl  = msg_W + (size_t)l * TT * HH * HH;
        const float* bl  = msg_b + (size_t)l * TT * HH;
        const float* Wih = (l == 0) ? g0Wih : (g1Wih + HH);
        int          ldw = (l == 0) ? HH : 2 * HH;
        const float* Whh = (l == 0) ? g0Whh : g1Whh;
        const float* bih = (l == 0) ? g0bih : nullptr;
        const float* cin = (l == 0) ? nullptr : gxx;
        const float* bhh = (l == 0) ? g0bhh : g1bhh;

        for (int step = 0; step < 3; step++) {
            // all h-GEMMs in one launch: m_0..m_3 and gh
            gemm_hcomb<<<gridHC, 256, GEMM_SMEM>>>(h, Wl, bl, m, Whh, bhh, gh, NN);

            // inc[tgt] += m_t[src]
            scatter_kernel<<<scatBlocks, 256>>>(edges, m, inc);

            // gx = inc @ Wih^T (+gxx | +bih)
            gemm_tc<<<gridG, 256, GEMM_SMEM>>>(inc, Wih, ldw, cin,
                                               gx, G3H, bih, NN);

            // gates: h updated in place, inc zeroed for next step
            gates_kernel<<<(NN * HH + 255) / 256, 256>>>(h, gx, gh, inc);
        }
    }
}

// round 14
// speedup vs baseline: 1.5133x; 1.0326x over previous
#include <cuda_runtime.h>
#include <cstdint>
#include <math.h>

#define NN 50000
#define HH 128
#define TT 4
#define EE 150000
#define G3H 384

// ---------------- scratch ---------------------------------------------------
__device__ __align__(16) float g_inc[(size_t)NN * HH];
__device__ __align__(16) float g_m  [(size_t)TT * NN * HH];
__device__ __align__(16) float g_gx [(size_t)NN * G3H];
__device__ __align__(16) float g_gh [(size_t)NN * G3H];
__device__ __align__(16) float g_gxx[(size_t)NN * G3H];

// ---------------- utility kernels ------------------------------------------
__global__ void zero4_kernel(float4* __restrict__ p, int n4) {
    int i = blockIdx.x * blockDim.x + threadIdx.x;
    if (i < n4) p[i] = make_float4(0.f, 0.f, 0.f, 0.f);
}
__global__ void copy4_kernel(float4* __restrict__ dst, const float4* __restrict__ src, int n4) {
    int i = blockIdx.x * blockDim.x + threadIdx.x;
    if (i < n4) dst[i] = src[i];
}

// ---------------- scatter: inc[tgt] += m[t][src], 4 edges per warp ---------
__global__ void scatter_kernel(const int* __restrict__ edges,
                               const float* __restrict__ m,
                               float* __restrict__ inc) {
    int e0 = (blockIdx.x * 8 + (threadIdx.x >> 5)) * 4;
    int lane = threadIdx.x & 31;
    float4 v[4];
    int tgt[4];
    bool ok[4];
#pragma unroll
    for (int u = 0; u < 4; u++) {
        int e = e0 + u;
        ok[u] = (e < TT * EE);
        if (ok[u]) {
            int t   = e / EE;
            int src = edges[2 * e];
            tgt[u]  = edges[2 * e + 1];
            v[u] = *(const float4*)(m + ((size_t)t * NN + (size_t)src) * HH + lane * 4);
        }
    }
#pragma unroll
    for (int u = 0; u < 4; u++) {
        if (ok[u]) {
            float* dst = inc + (size_t)tgt[u] * HH + lane * 4;
            asm volatile("red.global.add.v4.f32 [%0], {%1, %2, %3, %4};"
                         :: "l"(dst), "f"(v[u].x), "f"(v[u].y), "f"(v[u].z), "f"(v[u].w)
                         : "memory");
        }
    }
}

// ---------------- common MMA bits ------------------------------------------
__device__ __forceinline__ void mma8(float* d, const uint32_t* a, const uint32_t* b) {
    asm volatile(
        "mma.sync.aligned.m16n8k8.row.col.f32.tf32.tf32.f32 "
        "{%0,%1,%2,%3}, {%4,%5,%6,%7}, {%8,%9}, {%0,%1,%2,%3};"
        : "+f"(d[0]), "+f"(d[1]), "+f"(d[2]), "+f"(d[3])
        : "r"(a[0]), "r"(a[1]), "r"(a[2]), "r"(a[3]), "r"(b[0]), "r"(b[1]));
}
__device__ __forceinline__ uint4 cvt4(float4 v) {
    uint4 u;
    asm("cvt.rna.tf32.f32 %0, %1;" : "=r"(u.x) : "f"(v.x));
    asm("cvt.rna.tf32.f32 %0, %1;" : "=r"(u.y) : "f"(v.y));
    asm("cvt.rna.tf32.f32 %0, %1;" : "=r"(u.z) : "f"(v.z));
    asm("cvt.rna.tf32.f32 %0, %1;" : "=r"(u.w) : "f"(v.w));
    return u;
}

extern __shared__ uint32_t gsm[];

#define KCH 64
#define SPITCH 68
#define ATILE (128 * SPITCH)
#define GEMM_SMEM (2 * ATILE * 4)

// core: one 128x128 C tile = A[row0:+128, :128] @ Bt[0:128, :128]^T (+bias +Cin)
// 128 threads, 4 warps in 2x2; warp tile 64x64 (16 FLOP per LDS byte).
__device__ __forceinline__ void gemm_core(
    const float* __restrict__ A,
    const float* __restrict__ Bt, int ldb,
    const float* __restrict__ Cin,
    float* __restrict__ C, int ldc, int ccol,
    const float* __restrict__ bias,
    int row0, int M) {
    uint32_t* As = gsm;
    uint32_t* Bs = gsm + ATILE;

    int tid  = threadIdx.x;
    int wid  = tid >> 5;
    int lane = tid & 31;
    int wm   = wid & 1;        // row half (64 rows)
    int wn   = wid >> 1;       // col half (64 cols)
    int g    = lane >> 2;
    int tg   = lane & 3;

    float acc[4][8][4];
#pragma unroll
    for (int i = 0; i < 4; i++)
#pragma unroll
        for (int j = 0; j < 8; j++)
#pragma unroll
            for (int k = 0; k < 4; k++) acc[i][j][k] = 0.f;

    for (int kc = 0; kc < 128; kc += KCH) {
#pragma unroll
        for (int i = 0; i < 16; i++) {
            int id = tid + 128 * i;
            int r  = id >> 4;
            int c4 = (id & 15) << 2;
            float4 va = make_float4(0.f, 0.f, 0.f, 0.f);
            if (row0 + r < M) va = *(const float4*)(A + (long)(row0 + r) * HH + kc + c4);
            *(uint4*)(As + r * SPITCH + c4) = cvt4(va);
            float4 vb = *(const float4*)(Bt + (long)r * ldb + kc + c4);
            *(uint4*)(Bs + r * SPITCH + c4) = cvt4(vb);
        }
        __syncthreads();
#pragma unroll
        for (int ks = 0; ks < 8; ks++) {
            int k0 = ks * 8;
            uint32_t af[4][4], bf[8][2];
#pragma unroll
            for (int mt = 0; mt < 4; mt++) {
                int r = wm * 64 + mt * 16 + g;
                af[mt][0] = As[(r    ) * SPITCH + k0 + tg];
                af[mt][1] = As[(r + 8) * SPITCH + k0 + tg];
                af[mt][2] = As[(r    ) * SPITCH + k0 + tg + 4];
                af[mt][3] = As[(r + 8) * SPITCH + k0 + tg + 4];
            }
#pragma unroll
            for (int nt = 0; nt < 8; nt++) {
                int c = wn * 64 + nt * 8 + g;
                bf[nt][0] = Bs[c * SPITCH + k0 + tg];
                bf[nt][1] = Bs[c * SPITCH + k0 + tg + 4];
            }
#pragma unroll
            for (int mt = 0; mt < 4; mt++)
#pragma unroll
                for (int nt = 0; nt < 8; nt++)
                    mma8(acc[mt][nt], af[mt], bf[nt]);
        }
        __syncthreads();
    }

#pragma unroll
    for (int mt = 0; mt < 4; mt++) {
        int r = row0 + wm * 64 + mt * 16 + g;
#pragma unroll
        for (int nt = 0; nt < 8; nt++) {
            int cl = wn * 64 + nt * 8 + 2 * tg;
            int c  = ccol + cl;
            float b0 = 0.f, b1 = 0.f;
            if (bias) { b0 = bias[cl]; b1 = bias[cl + 1]; }
            if (r < M) {
                float v0 = acc[mt][nt][0] + b0;
                float v1 = acc[mt][nt][1] + b1;
                if (Cin) {
                    float2 ci = *(const float2*)(Cin + (long)r * ldc + c);
                    v0 += ci.x; v1 += ci.y;
                }
                *(float2*)(C + (long)r * ldc + c) = make_float2(v0, v1);
            }
            if (r + 8 < M) {
                float v2 = acc[mt][nt][2] + b0;
                float v3 = acc[mt][nt][3] + b1;
                if (Cin) {
                    float2 ci = *(const float2*)(Cin + (long)(r + 8) * ldc + c);
                    v2 += ci.x; v3 += ci.y;
                }
                *(float2*)(C + (long)(r + 8) * ldc + c) = make_float2(v2, v3);
            }
        }
    }
}

// generic GEMM (for gxx / gx): grid (colTiles, rowBlocks)
__global__ __launch_bounds__(128, 2)
void gemm_tc(const float* __restrict__ A,
             const float* __restrict__ B, int ldb,
             const float* __restrict__ Cin,
             float* __restrict__ C, int ldc,
             const float* __restrict__ bias,
             int M) {
    int ct = blockIdx.x;
    gemm_core(A, B + (long)ct * 128 * ldb, ldb, Cin, C, ldc, ct * 128,
              bias ? (bias + ct * 128) : nullptr, blockIdx.y * 128, M);
}

// combined h-GEMMs. Order matters for L2: gh tiles first (z=0..2), then
// m_t (z=3..6) so m is L2-resident when the scatter gathers from it.
__global__ __launch_bounds__(128, 2)
void gemm_hcomb(const float* __restrict__ h,
                const float* __restrict__ msgW, const float* __restrict__ msgb,
                float* __restrict__ m,
                const float* __restrict__ Whh, const float* __restrict__ bhh,
                float* __restrict__ gh, int M) {
    int z = blockIdx.z;
    if (z < 3) {
        gemm_core(h, Whh + (long)z * 128 * HH, HH, nullptr,
                  gh, G3H, z * 128, bhh + z * 128,
                  blockIdx.y * 128, M);
    } else {
        int t = z - 3;
        gemm_core(h, msgW + (long)t * HH * HH, HH, nullptr,
                  m + (size_t)t * NN * HH, HH, 0, msgb + t * HH,
                  blockIdx.y * 128, M);
    }
}

// ---------------- GRU gates (float4; + zero inc for next step) -------------
__global__ void gates_kernel(float* __restrict__ h,
                             const float* __restrict__ gx,
                             const float* __restrict__ gh,
                             float* __restrict__ inc) {
    int i4 = blockIdx.x * blockDim.x + threadIdx.x;
    if (i4 >= NN * HH / 4) return;
    int n  = i4 >> 5;
    int f4 = (i4 & 31) << 2;
    long base = (long)n * G3H + f4;
    float4 xr = *(const float4*)(gx + base);
    float4 xz = *(const float4*)(gx + base + 128);
    float4 xn = *(const float4*)(gx + base + 256);
    float4 hr = *(const float4*)(gh + base);
    float4 hz = *(const float4*)(gh + base + 128);
    float4 hn = *(const float4*)(gh + base + 256);
    float4 hv = *(const float4*)(h + (long)i4 * 4);
    float4 o;
    {
        float r = 1.f / (1.f + expf(-(xr.x + hr.x)));
        float z = 1.f / (1.f + expf(-(xz.x + hz.x)));
        float nn = tanhf(xn.x + r * hn.x);
        o.x = (1.f - z) * nn + z * hv.x;
    }
    {
        float r = 1.f / (1.f + expf(-(xr.y + hr.y)));
        float z = 1.f / (1.f + expf(-(xz.y + hz.y)));
        float nn = tanhf(xn.y + r * hn.y);
        o.y = (1.f - z) * nn + z * hv.y;
    }
    {
        float r = 1.f / (1.f + expf(-(xr.z + hr.z)));
        float z = 1.f / (1.f + expf(-(xz.z + hz.z)));
        float nn = tanhf(xn.z + r * hn.z);
        o.z = (1.f - z) * nn + z * hv.z;
    }
    {
        float r = 1.f / (1.f + expf(-(xr.w + hr.w)));
        float z = 1.f / (1.f + expf(-(xz.w + hz.w)));
        float nn = tanhf(xn.w + r * hn.w);
        o.w = (1.f - z) * nn + z * hv.w;
    }
    *(float4*)(h + (long)i4 * 4) = o;
    *(float4*)(inc + (long)i4 * 4) = make_float4(0.f, 0.f, 0.f, 0.f);
}

// ---------------- orchestration --------------------------------------------
extern "C" void kernel_launch(void* const* d_in, const int* in_sizes, int n_in,
                              void* d_out, int out_size) {
    const float* x      = (const float*)d_in[0];
    const int*   edges  = (const int*)  d_in[1];
    const float* msg_W  = (const float*)d_in[2];
    const float* msg_b  = (const float*)d_in[3];
    const float* g0Wih  = (const float*)d_in[4];
    const float* g0Whh  = (const float*)d_in[5];
    const float* g0bih  = (const float*)d_in[6];
    const float* g0bhh  = (const float*)d_in[7];
    const float* g1Wih  = (const float*)d_in[8];
    const float* g1Whh  = (const float*)d_in[9];
    const float* g1bih  = (const float*)d_in[10];
    const float* g1bhh  = (const float*)d_in[11];
    float* h = (float*)d_out;            // h lives in the output buffer

    float *inc, *m, *gx, *gh, *gxx;
    cudaGetSymbolAddress((void**)&inc, g_inc);
    cudaGetSymbolAddress((void**)&m,   g_m);
    cudaGetSymbolAddress((void**)&gx,  g_gx);
    cudaGetSymbolAddress((void**)&gh,  g_gh);
    cudaGetSymbolAddress((void**)&gxx, g_gxx);

    static int inited = 0;
    if (!inited) {
        cudaFuncSetAttribute(gemm_tc,    cudaFuncAttributeMaxDynamicSharedMemorySize, GEMM_SMEM);
        cudaFuncSetAttribute(gemm_hcomb, cudaFuncAttributeMaxDynamicSharedMemorySize, GEMM_SMEM);
        inited = 1;
    }

    const int nh4 = NN * HH / 4;
    const int nBlk = (NN + 127) / 128;        // 391
    const int nWarps4 = (TT * EE + 3) / 4;
    const int scatBlocks = (nWarps4 + 7) / 8;

    dim3 gridHC(1, nBlk, 7);
    dim3 gridG (3, nBlk, 1);

    // h = x ; inc = 0
    copy4_kernel<<<(nh4 + 255) / 256, 256>>>((float4*)h, (const float4*)x, nh4);
    zero4_kernel<<<(nh4 + 255) / 256, 256>>>((float4*)inc, nh4);

    // gxx = x @ Wih1[:, :128]^T + bih1
    gemm_tc<<<gridG, 128, GEMM_SMEM>>>(x, g1Wih, 2 * HH, nullptr,
                                       gxx, G3H, g1bih, NN);

    for (int l = 0; l < 2; l++) {
        const float* Wl  = msg_W + (size_t)l * TT * HH * HH;
        const float* bl  = msg_b + (size_t)l * TT * HH;
        const float* Wih = (l == 0) ? g0Wih : (g1Wih + HH);
        int          ldw = (l == 0) ? HH : 2 * HH;
        const float* Whh = (l == 0) ? g0Whh : g1Whh;
        const float* bih = (l == 0) ? g0bih : nullptr;
        const float* cin = (l == 0) ? nullptr : gxx;
        const float* bhh = (l == 0) ? g0bhh : g1bhh;

        for (int step = 0; step < 3; step++) {
            // all h-GEMMs in one launch: gh tiles then m_0..m_3
            gemm_hcomb<<<gridHC, 128, GEMM_SMEM>>>(h, Wl, bl, m, Whh, bhh, gh, NN);

            // inc[tgt] += m_t[src]
            scatter_kernel<<<scatBlocks, 256>>>(edges, m, inc);

            // gx = inc @ Wih^T (+gxx | +bih)
            gemm_tc<<<gridG, 128, GEMM_SMEM>>>(inc, Wih, ldw, cin,
                                               gx, G3H, bih, NN);

            // gates: h updated in place, inc zeroed for next step
            gates_kernel<<<(nh4 + 255) / 256, 256>>>(h, gx, gh, inc);
        }
    }
}

// round 16
// speedup vs baseline: 1.5322x; 1.0125x over previous
#include <cuda_runtime.h>
#include <cstdint>
#include <math.h>

#define NN 50000
#define HH 128
#define TT 4
#define EE 150000
#define G3H 384
#define NE (TT * EE)

// ---------------- scratch ---------------------------------------------------
__device__ __align__(16) float g_inc[(size_t)NN * HH];
__device__ __align__(16) float g_m  [(size_t)TT * NN * HH];
__device__ __align__(16) float g_gx [(size_t)NN * G3H];
__device__ __align__(16) float g_gh [(size_t)NN * G3H];
__device__ __align__(16) float g_gxx[(size_t)NN * G3H];
__device__ int g_count [NN];
__device__ int g_starts[NN + 1];
__device__ int g_cursor[NN];
__device__ int g_elist [NE];

// ---------------- utility kernels ------------------------------------------
__global__ void zeroi_kernel(int* __restrict__ p, int n) {
    int i = blockIdx.x * blockDim.x + threadIdx.x;
    if (i < n) p[i] = 0;
}
__global__ void copy4_kernel(float4* __restrict__ dst, const float4* __restrict__ src, int n4) {
    int i = blockIdx.x * blockDim.x + threadIdx.x;
    if (i < n4) dst[i] = src[i];
}

// ---------------- CSR build (once per launch; edges constant) --------------
__global__ void hist_kernel(const int* __restrict__ edges, int* __restrict__ count) {
    int i = blockIdx.x * blockDim.x + threadIdx.x;
    if (i < NE) atomicAdd(count + edges[2 * i + 1], 1);
}

__global__ void scan_kernel(const int* __restrict__ count,
                            int* __restrict__ starts, int* __restrict__ cursor) {
    __shared__ int sm[1024];
    __shared__ int carry;
    int tid = threadIdx.x;
    if (tid == 0) carry = 0;
    __syncthreads();
    for (int base = 0; base < NN; base += 1024) {
        int v = (base + tid < NN) ? count[base + tid] : 0;
        sm[tid] = v;
        __syncthreads();
#pragma unroll
        for (int off = 1; off < 1024; off <<= 1) {
            int t = (tid >= off) ? sm[tid - off] : 0;
            __syncthreads();
            sm[tid] += t;
            __syncthreads();
        }
        int excl = sm[tid] - v;
        if (base + tid < NN) {
            int s = carry + excl;
            starts[base + tid] = s;
            cursor[base + tid] = s;
        }
        __syncthreads();
        if (tid == 0) carry += sm[1023];
        __syncthreads();
    }
    if (tid == 0) starts[NN] = carry;
}

__global__ void fill_kernel(const int* __restrict__ edges,
                            int* __restrict__ cursor, int* __restrict__ elist) {
    int i = blockIdx.x * blockDim.x + threadIdx.x;
    if (i >= NE) return;
    int t   = i / EE;
    int src = edges[2 * i];
    int tgt = edges[2 * i + 1];
    int pos = atomicAdd(cursor + tgt, 1);
    elist[pos] = t * NN + src;
}

// ---------------- gather: inc[n] = sum over in-edges of m[elist[i]] --------
__global__ void gather_kernel(const int* __restrict__ starts,
                              const int* __restrict__ elist,
                              const float* __restrict__ m,
                              float* __restrict__ inc) {
    int n = blockIdx.x * 8 + (threadIdx.x >> 5);
    if (n >= NN) return;
    int lane = threadIdx.x & 31;
    int beg = starts[n], end = starts[n + 1];
    float4 a0 = make_float4(0.f, 0.f, 0.f, 0.f);
    float4 a1 = make_float4(0.f, 0.f, 0.f, 0.f);
    float4 a2 = make_float4(0.f, 0.f, 0.f, 0.f);
    float4 a3 = make_float4(0.f, 0.f, 0.f, 0.f);
    int i = beg;
    for (; i + 3 < end; i += 4) {
        int s0 = elist[i], s1 = elist[i + 1], s2 = elist[i + 2], s3 = elist[i + 3];
        float4 v0 = *(const float4*)(m + (size_t)s0 * HH + lane * 4);
        float4 v1 = *(const float4*)(m + (size_t)s1 * HH + lane * 4);
        float4 v2 = *(const float4*)(m + (size_t)s2 * HH + lane * 4);
        float4 v3 = *(const float4*)(m + (size_t)s3 * HH + lane * 4);
        a0.x += v0.x; a0.y += v0.y; a0.z += v0.z; a0.w += v0.w;
        a1.x += v1.x; a1.y += v1.y; a1.z += v1.z; a1.w += v1.w;
        a2.x += v2.x; a2.y += v2.y; a2.z += v2.z; a2.w += v2.w;
        a3.x += v3.x; a3.y += v3.y; a3.z += v3.z; a3.w += v3.w;
    }
    for (; i < end; i++) {
        int s0 = elist[i];
        float4 v0 = *(const float4*)(m + (size_t)s0 * HH + lane * 4);
        a0.x += v0.x; a0.y += v0.y; a0.z += v0.z; a0.w += v0.w;
    }
    a0.x += a1.x + a2.x + a3.x;
    a0.y += a1.y + a2.y + a3.y;
    a0.z += a1.z + a2.z + a3.z;
    a0.w += a1.w + a2.w + a3.w;
    *(float4*)(inc + (size_t)n * HH + lane * 4) = a0;
}

// ---------------- common MMA bits ------------------------------------------
__device__ __forceinline__ void mma8(float* d, const uint32_t* a, const uint32_t* b) {
    asm volatile(
        "mma.sync.aligned.m16n8k8.row.col.f32.tf32.tf32.f32 "
        "{%0,%1,%2,%3}, {%4,%5,%6,%7}, {%8,%9}, {%0,%1,%2,%3};"
        : "+f"(d[0]), "+f"(d[1]), "+f"(d[2]), "+f"(d[3])
        : "r"(a[0]), "r"(a[1]), "r"(a[2]), "r"(a[3]), "r"(b[0]), "r"(b[1]));
}
__device__ __forceinline__ uint4 cvt4(float4 v) {
    uint4 u;
    asm("cvt.rna.tf32.f32 %0, %1;" : "=r"(u.x) : "f"(v.x));
    asm("cvt.rna.tf32.f32 %0, %1;" : "=r"(u.y) : "f"(v.y));
    asm("cvt.rna.tf32.f32 %0, %1;" : "=r"(u.z) : "f"(v.z));
    asm("cvt.rna.tf32.f32 %0, %1;" : "=r"(u.w) : "f"(v.w));
    return u;
}

extern __shared__ uint32_t gsm[];

#define KCH 64
#define SPITCH 68
#define ATILE (128 * SPITCH)
#define GEMM_SMEM (2 * ATILE * 4)

// core: one 128x128 C tile = A[row0:+128, :128] @ Bt[0:128, :128]^T (+bias +Cin)
__device__ __forceinline__ void gemm_core(
    const float* __restrict__ A,
    const float* __restrict__ Bt, int ldb,
    const float* __restrict__ Cin,
    float* __restrict__ C, int ldc, int ccol,
    const float* __restrict__ bias,
    int row0, int M) {
    uint32_t* As = gsm;
    uint32_t* Bs = gsm + ATILE;

    int tid  = threadIdx.x;
    int wid  = tid >> 5;
    int lane = tid & 31;
    int wm   = wid & 1;
    int wn   = wid >> 1;
    int g    = lane >> 2;
    int tg   = lane & 3;

    float acc[4][8][4];
#pragma unroll
    for (int i = 0; i < 4; i++)
#pragma unroll
        for (int j = 0; j < 8; j++)
#pragma unroll
            for (int k = 0; k < 4; k++) acc[i][j][k] = 0.f;

    for (int kc = 0; kc < 128; kc += KCH) {
#pragma unroll
        for (int i = 0; i < 16; i++) {
            int id = tid + 128 * i;
            int r  = id >> 4;
            int c4 = (id & 15) << 2;
            float4 va = make_float4(0.f, 0.f, 0.f, 0.f);
            if (row0 + r < M) va = *(const float4*)(A + (long)(row0 + r) * HH + kc + c4);
            *(uint4*)(As + r * SPITCH + c4) = cvt4(va);
            float4 vb = *(const float4*)(Bt + (long)r * ldb + kc + c4);
            *(uint4*)(Bs + r * SPITCH + c4) = cvt4(vb);
        }
        __syncthreads();
#pragma unroll
        for (int ks = 0; ks < 8; ks++) {
            int k0 = ks * 8;
            uint32_t af[4][4], bf[8][2];
#pragma unroll
            for (int mt = 0; mt < 4; mt++) {
                int r = wm * 64 + mt * 16 + g;
                af[mt][0] = As[(r    ) * SPITCH + k0 + tg];
                af[mt][1] = As[(r + 8) * SPITCH + k0 + tg];
                af[mt][2] = As[(r    ) * SPITCH + k0 + tg + 4];
                af[mt][3] = As[(r + 8) * SPITCH + k0 + tg + 4];
            }
#pragma unroll
            for (int nt = 0; nt < 8; nt++) {
                int c = wn * 64 + nt * 8 + g;
                bf[nt][0] = Bs[c * SPITCH + k0 + tg];
                bf[nt][1] = Bs[c * SPITCH + k0 + tg + 4];
            }
#pragma unroll
            for (int mt = 0; mt < 4; mt++)
#pragma unroll
                for (int nt = 0; nt < 8; nt++)
                    mma8(acc[mt][nt], af[mt], bf[nt]);
        }
        __syncthreads();
    }

#pragma unroll
    for (int mt = 0; mt < 4; mt++) {
        int r = row0 + wm * 64 + mt * 16 + g;
#pragma unroll
        for (int nt = 0; nt < 8; nt++) {
            int cl = wn * 64 + nt * 8 + 2 * tg;
            int c  = ccol + cl;
            float b0 = 0.f, b1 = 0.f;
            if (bias) { b0 = bias[cl]; b1 = bias[cl + 1]; }
            if (r < M) {
                float v0 = acc[mt][nt][0] + b0;
                float v1 = acc[mt][nt][1] + b1;
                if (Cin) {
                    float2 ci = *(const float2*)(Cin + (long)r * ldc + c);
                    v0 += ci.x; v1 += ci.y;
                }
                *(float2*)(C + (long)r * ldc + c) = make_float2(v0, v1);
            }
            if (r + 8 < M) {
                float v2 = acc[mt][nt][2] + b0;
                float v3 = acc[mt][nt][3] + b1;
                if (Cin) {
                    float2 ci = *(const float2*)(Cin + (long)(r + 8) * ldc + c);
                    v2 += ci.x; v3 += ci.y;
                }
                *(float2*)(C + (long)(r + 8) * ldc + c) = make_float2(v2, v3);
            }
        }
    }
}

__global__ __launch_bounds__(128, 2)
void gemm_tc(const float* __restrict__ A,
             const float* __restrict__ B, int ldb,
             const float* __restrict__ Cin,
             float* __restrict__ C, int ldc,
             const float* __restrict__ bias,
             int M) {
    int ct = blockIdx.x;
    gemm_core(A, B + (long)ct * 128 * ldb, ldb, Cin, C, ldc, ct * 128,
              bias ? (bias + ct * 128) : nullptr, blockIdx.y * 128, M);
}

// combined h-GEMMs; gh tiles first, m_t last (m freshly L2-resident for gather)
__global__ __launch_bounds__(128, 2)
void gemm_hcomb(const float* __restrict__ h,
                const float* __restrict__ msgW, const float* __restrict__ msgb,
                float* __restrict__ m,
                const float* __restrict__ Whh, const float* __restrict__ bhh,
                float* __restrict__ gh, int M) {
    int z = blockIdx.z;
    if (z < 3) {
        gemm_core(h, Whh + (long)z * 128 * HH, HH, nullptr,
                  gh, G3H, z * 128, bhh + z * 128,
                  blockIdx.y * 128, M);
    } else {
        int t = z - 3;
        gemm_core(h, msgW + (long)t * HH * HH, HH, nullptr,
                  m + (size_t)t * NN * HH, HH, 0, msgb + t * HH,
                  blockIdx.y * 128, M);
    }
}

// ---------------- GRU gates (float4, h in place) ---------------------------
__global__ void gates_kernel(float* __restrict__ h,
                             const float* __restrict__ gx,
                             const float* __restrict__ gh) {
    int i4 = blockIdx.x * blockDim.x + threadIdx.x;
    if (i4 >= NN * HH / 4) return;
    int n  = i4 >> 5;
    int f4 = (i4 & 31) << 2;
    long base = (long)n * G3H + f4;
    float4 xr = *(const float4*)(gx + base);
    float4 xz = *(const float4*)(gx + base + 128);
    float4 xn = *(const float4*)(gx + base + 256);
    float4 hr = *(const float4*)(gh + base);
    float4 hz = *(const float4*)(gh + base + 128);
    float4 hn = *(const float4*)(gh + base + 256);
    float4 hv = *(const float4*)(h + (long)i4 * 4);
    float4 o;
    {
        float r = 1.f / (1.f + expf(-(xr.x + hr.x)));
        float z = 1.f / (1.f + expf(-(xz.x + hz.x)));
        float nn = tanhf(xn.x + r * hn.x);
        o.x = (1.f - z) * nn + z * hv.x;
    }
    {
        float r = 1.f / (1.f + expf(-(xr.y + hr.y)));
        float z = 1.f / (1.f + expf(-(xz.y + hz.y)));
        float nn = tanhf(xn.y + r * hn.y);
        o.y = (1.f - z) * nn + z * hv.y;
    }
    {
        float r = 1.f / (1.f + expf(-(xr.z + hr.z)));
        float z = 1.f / (1.f + expf(-(xz.z + hz.z)));
        float nn = tanhf(xn.z + r * hn.z);
        o.z = (1.f - z) * nn + z * hv.z;
    }
    {
        float r = 1.f / (1.f + expf(-(xr.w + hr.w)));
        float z = 1.f / (1.f + expf(-(xz.w + hz.w)));
        float nn = tanhf(xn.w + r * hn.w);
        o.w = (1.f - z) * nn + z * hv.w;
    }
    *(float4*)(h + (long)i4 * 4) = o;
}

// ---------------- orchestration --------------------------------------------
extern "C" void kernel_launch(void* const* d_in, const int* in_sizes, int n_in,
                              void* d_out, int out_size) {
    const float* x      = (const float*)d_in[0];
    const int*   edges  = (const int*)  d_in[1];
    const float* msg_W  = (const float*)d_in[2];
    const float* msg_b  = (const float*)d_in[3];
    const float* g0Wih  = (const float*)d_in[4];
    const float* g0Whh  = (const float*)d_in[5];
    const float* g0bih  = (const float*)d_in[6];
    const float* g0bhh  = (const float*)d_in[7];
    const float* g1Wih  = (const float*)d_in[8];
    const float* g1Whh  = (const float*)d_in[9];
    const float* g1bih  = (const float*)d_in[10];
    const float* g1bhh  = (const float*)d_in[11];
    float* h = (float*)d_out;            // h lives in the output buffer

    float *inc, *m, *gx, *gh, *gxx;
    int *count, *starts, *cursor, *elist;
    cudaGetSymbolAddress((void**)&inc,    g_inc);
    cudaGetSymbolAddress((void**)&m,      g_m);
    cudaGetSymbolAddress((void**)&gx,     g_gx);
    cudaGetSymbolAddress((void**)&gh,     g_gh);
    cudaGetSymbolAddress((void**)&gxx,    g_gxx);
    cudaGetSymbolAddress((void**)&count,  g_count);
    cudaGetSymbolAddress((void**)&starts, g_starts);
    cudaGetSymbolAddress((void**)&cursor, g_cursor);
    cudaGetSymbolAddress((void**)&elist,  g_elist);

    static int inited = 0;
    if (!inited) {
        cudaFuncSetAttribute(gemm_tc,    cudaFuncAttributeMaxDynamicSharedMemorySize, GEMM_SMEM);
        cudaFuncSetAttribute(gemm_hcomb, cudaFuncAttributeMaxDynamicSharedMemorySize, GEMM_SMEM);
        inited = 1;
    }

    const int nh4 = NN * HH / 4;
    const int nBlk = (NN + 127) / 128;        // 391

    dim3 gridHC(1, nBlk, 7);
    dim3 gridG (3, nBlk, 1);

    // --- CSR build (edges constant across all steps) ---
    zeroi_kernel<<<(NN + 255) / 256, 256>>>(count, NN);
    hist_kernel<<<(NE + 255) / 256, 256>>>(edges, count);
    scan_kernel<<<1, 1024>>>(count, starts, cursor);
    fill_kernel<<<(NE + 255) / 256, 256>>>(edges, cursor, elist);

    // h = x
    copy4_kernel<<<(nh4 + 255) / 256, 256>>>((float4*)h, (const float4*)x, nh4);

    // gxx = x @ Wih1[:, :128]^T + bih1
    gemm_tc<<<gridG, 128, GEMM_SMEM>>>(x, g1Wih, 2 * HH, nullptr,
                                       gxx, G3H, g1bih, NN);

    for (int l = 0; l < 2; l++) {
        const float* Wl  = msg_W + (size_t)l * TT * HH * HH;
        const float* bl  = msg_b + (size_t)l * TT * HH;
        const float* Wih = (l == 0) ? g0Wih : (g1Wih + HH);
        int          ldw = (l == 0) ? HH : 2 * HH;
        const float* Whh = (l == 0) ? g0Whh : g1Whh;
        const float* bih = (l == 0) ? g0bih : nullptr;
        const float* cin = (l == 0) ? nullptr : gxx;
        const float* bhh = (l == 0) ? g0bhh : g1bhh;

        for (int step = 0; step < 3; step++) {
            // all h-GEMMs in one launch: gh tiles then m_0..m_3
            gemm_hcomb<<<gridHC, 128, GEMM_SMEM>>>(h, Wl, bl, m, Whh, bhh, gh, NN);

            // inc[n] = sum of m over in-edges (atomic-free)
            gather_kernel<<<(NN + 7) / 8, 256>>>(starts, elist, m, inc);

            // gx = inc @ Wih^T (+gxx | +bih)
            gemm_tc<<<gridG, 128, GEMM_SMEM>>>(inc, Wih, ldw, cin,
                                               gx, G3H, bih, NN);

            // gates: h updated in place
            gates_kernel<<<(nh4 + 255) / 256, 256>>>(h, gx, gh);
        }
    }
}